// round 1
// baseline (speedup 1.0000x reference)
#include <cuda_runtime.h>
#include <cstdint>

// ---------------- problem constants ----------------
#define B_    16
#define T_    8
#define NB_   4
#define CIN   2048
#define CI    512
#define HF    14
#define HW    196          // 14*14
#define NROI  512          // B*T*NB
#define MBINS 9            // PH*PW
#define M1    (NROI*MBINS) // 4608
#define KFEAT (CI*MBINS)   // 4608

// ---------------- scratch (static device memory; no allocs) ----------------
__device__ float d_rois[(size_t)M1 * CIN];       // [roi*9+bin][c]   ~37.7MB
__device__ float d_feats[(size_t)NROI * KFEAT];  // [roi][o*9+bin]   ~9.4MB
__device__ float d_regpart[4 * NROI * CI];       // split-K partials ~4MB
__device__ float d_objf[32 * CI];
__device__ float d_pooled[16 * CI];
__device__ float d_h1[32 * CI];
__device__ float d_g1[16 * CI];
__device__ int   d_tidx[NROI * MBINS * 16];
__device__ float d_tw[NROI * MBINS * 16];

// ============================================================
// K1: build ROI-align tap table: per (roi,bin) 16 (pixel, weight)
// ============================================================
__global__ void build_table(const float* __restrict__ boxes) {
    int roi = blockIdx.x * blockDim.x + threadIdx.x;
    if (roi >= NROI) return;
    float cx = boxes[roi * 4 + 0], cy = boxes[roi * 4 + 1];
    float w  = boxes[roi * 4 + 2], h  = boxes[roi * 4 + 3];
    const float s = 14.0f / 224.0f;
    float x1 = (cx - 0.5f * w) * 224.0f * s;
    float y1 = (cy - 0.5f * h) * 224.0f * s;
    float x2 = (cx + 0.5f * w) * 224.0f * s;
    float y2 = (cy + 0.5f * h) * 224.0f * s;
    float rw = fmaxf(x2 - x1, 1.0f), rh = fmaxf(y2 - y1, 1.0f);
    float bw = rw / 3.0f, bh = rh / 3.0f;

    float ys[6], xs[6];
#pragma unroll
    for (int p = 0; p < 3; ++p)
#pragma unroll
        for (int i = 0; i < 2; ++i) {
            ys[p * 2 + i] = y1 + p * bh + (i + 0.5f) * bh * 0.5f;
            xs[p * 2 + i] = x1 + p * bw + (i + 0.5f) * bw * 0.5f;
        }

#pragma unroll
    for (int ph = 0; ph < 3; ++ph)
#pragma unroll
        for (int pw = 0; pw < 3; ++pw) {
            int bin = ph * 3 + pw;
#pragma unroll
            for (int iy = 0; iy < 2; ++iy)
#pragma unroll
                for (int ix = 0; ix < 2; ++ix) {
                    int smp = iy * 2 + ix;
                    float yy = ys[ph * 2 + iy];
                    float xx = xs[pw * 2 + ix];
                    bool valid = (yy > -1.0f) && (yy < 14.0f) && (xx > -1.0f) && (xx < 14.0f);
                    float y = fminf(fmaxf(yy, 0.0f), 13.0f);
                    float x = fminf(fmaxf(xx, 0.0f), 13.0f);
                    int y0 = (int)floorf(y), x0 = (int)floorf(x);
                    int y1i = min(y0 + 1, 13), x1i = min(x0 + 1, 13);
                    float ly = y - (float)y0, lx = x - (float)x0;
                    float hy = 1.0f - ly, hx = 1.0f - lx;
                    float q = valid ? 0.25f : 0.0f;   // fold the SRxSR mean
                    int base = ((roi * 9 + bin) * 4 + smp) * 4;
                    d_tidx[base + 0] = y0 * HF + x0;  d_tw[base + 0] = hy * hx * q;
                    d_tidx[base + 1] = y0 * HF + x1i; d_tw[base + 1] = hy * lx * q;
                    d_tidx[base + 2] = y1i * HF + x0; d_tw[base + 2] = ly * hx * q;
                    d_tidx[base + 3] = y1i * HF + x1i; d_tw[base + 3] = ly * lx * q;
                }
        }
}

// ============================================================
// K2: pooling in 2048-channel space (ROI(x), conv commuted out)
// block = (bt, c-chunk of 32); 288 threads
// ============================================================
__global__ __launch_bounds__(288) void pool_kernel(const float* __restrict__ x) {
    __shared__ float pl[32][197];    // 197 stride: conflict-free (197%32=5)
    __shared__ int   tix[576];
    __shared__ float twt[576];
    int bt = blockIdx.y;
    int c0 = blockIdx.x * 32;
    int tid = threadIdx.x;

    // x layout (B, C, T, H, W); plane x[b, c, t, :, :] is 196 contiguous floats
    size_t base = ((size_t)(bt >> 3) * CIN + c0) * (size_t)(T_ * HW) + (size_t)(bt & 7) * HW;
    for (int i = tid; i < 32 * HW; i += 288) {
        int ci = i / HW, p = i - ci * HW;
        pl[ci][p] = x[base + (size_t)ci * (T_ * HW) + p];
    }
    int tb = bt * 576;   // 4 rois * 9 bins * 16 taps for this bt
    for (int i = tid; i < 576; i += 288) {
        tix[i] = d_tidx[tb + i];
        twt[i] = d_tw[tb + i];
    }
    __syncthreads();

    for (int oid = tid; oid < 1152; oid += 288) {
        int ci = oid & 31;
        int e  = oid >> 5;            // nb*9+bin (warp-uniform: 288 % 32 == 0)
        const int*   ip = &tix[e * 16];
        const float* wp = &twt[e * 16];
        float acc = 0.0f;
#pragma unroll
        for (int t = 0; t < 16; ++t) acc += wp[t] * pl[ci][ip[t]];
        d_rois[(size_t)(bt * 36 + e) * CIN + c0 + ci] = acc;
    }
}

// ============================================================
// K3: GEMM1 (TN): feats = rois2048[4608,2048] x conv5_w[512,2048]^T
//     C written as feats[roi][o*9+bin]; 128x128x16 tiles, 8x8/thread
// ============================================================
__global__ __launch_bounds__(256) void gemm1(const float* __restrict__ Bw) {
    const int K = CIN;
    __shared__ float As[2][16][128];
    __shared__ float Bs[2][16][128];
    int bm = blockIdx.y * 128;
    int bn = blockIdx.x * 128;
    int tid = threadIdx.x;
    int tm = (tid >> 4) << 3;
    int tn = (tid & 15) << 3;

    float acc[8][8];
#pragma unroll
    for (int i = 0; i < 8; ++i)
#pragma unroll
        for (int j = 0; j < 8; ++j) acc[i][j] = 0.0f;

    float4 pa[2], pb[2];

    auto ldg = [&](int kk) {
#pragma unroll
        for (int it = 0; it < 2; ++it) {
            int idx = tid + (it << 8);
            int row = idx >> 2, kq = (idx & 3) << 2;
            pa[it] = *(const float4*)&d_rois[(size_t)(bm + row) * K + kk + kq];
            pb[it] = *(const float4*)&Bw[(size_t)(bn + row) * K + kk + kq];
        }
    };
    auto sts = [&](int buf) {
#pragma unroll
        for (int it = 0; it < 2; ++it) {
            int idx = tid + (it << 8);
            int row = idx >> 2, kq = (idx & 3) << 2;
            As[buf][kq + 0][row] = pa[it].x; As[buf][kq + 1][row] = pa[it].y;
            As[buf][kq + 2][row] = pa[it].z; As[buf][kq + 3][row] = pa[it].w;
            Bs[buf][kq + 0][row] = pb[it].x; Bs[buf][kq + 1][row] = pb[it].y;
            Bs[buf][kq + 2][row] = pb[it].z; Bs[buf][kq + 3][row] = pb[it].w;
        }
    };

    ldg(0); sts(0); __syncthreads();
    const int NK = K / 16;
    for (int t = 0; t < NK; ++t) {
        int cur = t & 1;
        if (t + 1 < NK) ldg((t + 1) * 16);
#pragma unroll
        for (int k = 0; k < 16; ++k) {
            float a[8], b[8];
            *(float4*)&a[0] = *(float4*)&As[cur][k][tm];
            *(float4*)&a[4] = *(float4*)&As[cur][k][tm + 4];
            *(float4*)&b[0] = *(float4*)&Bs[cur][k][tn];
            *(float4*)&b[4] = *(float4*)&Bs[cur][k][tn + 4];
#pragma unroll
            for (int i = 0; i < 8; ++i)
#pragma unroll
                for (int j = 0; j < 8; ++j) acc[i][j] += a[i] * b[j];
        }
        if (t + 1 < NK) sts(cur ^ 1);
        __syncthreads();
    }

    // store: m = roi*9+bin -> feats[roi][o*9+bin]
#pragma unroll
    for (int i = 0; i < 8; ++i) {
        int m = bm + tm + i;
        int roi = m / 9, bin = m - roi * 9;
        float* cp = &d_feats[(size_t)roi * KFEAT + bin];
#pragma unroll
        for (int j = 0; j < 8; ++j) cp[(bn + tn + j) * 9] = acc[i][j];
    }
}

// ============================================================
// K4: GEMM2 (NN, split-K=4): regpart = feats[512,4608] x re_w[4608,512]
//     64x64x16 tiles, 4x4/thread; grid (8,8,4)
// ============================================================
__global__ __launch_bounds__(256) void gemm2(const float* __restrict__ Bw) {
    const int K = KFEAT;
    __shared__ float As[2][16][64];
    __shared__ float Bs[2][16][64];
    int bm = blockIdx.y * 64;
    int bn = blockIdx.x * 64;
    int part = blockIdx.z;
    int k0 = part * 1152;
    int tid = threadIdx.x;
    int tm = (tid >> 4) << 2;
    int tn = (tid & 15) << 2;

    float acc[4][4];
#pragma unroll
    for (int i = 0; i < 4; ++i)
#pragma unroll
        for (int j = 0; j < 4; ++j) acc[i][j] = 0.0f;

    float4 pa, pb;
    int arow = tid >> 2, akq = (tid & 3) << 2;
    int bkr  = tid >> 4, bnq = (tid & 15) << 2;

    auto ldg = [&](int kk) {
        pa = *(const float4*)&d_feats[(size_t)(bm + arow) * K + kk + akq];
        pb = *(const float4*)&Bw[(size_t)(kk + bkr) * CI + bn + bnq];
    };
    auto sts = [&](int buf) {
        As[buf][akq + 0][arow] = pa.x; As[buf][akq + 1][arow] = pa.y;
        As[buf][akq + 2][arow] = pa.z; As[buf][akq + 3][arow] = pa.w;
        *(float4*)&Bs[buf][bkr][bnq] = pb;
    };

    ldg(k0); sts(0); __syncthreads();
    for (int t = 0; t < 72; ++t) {
        int cur = t & 1;
        if (t < 71) ldg(k0 + (t + 1) * 16);
#pragma unroll
        for (int k = 0; k < 16; ++k) {
            float a[4], b[4];
            *(float4*)a = *(float4*)&As[cur][k][tm];
            *(float4*)b = *(float4*)&Bs[cur][k][tn];
#pragma unroll
            for (int i = 0; i < 4; ++i)
#pragma unroll
                for (int j = 0; j < 4; ++j) acc[i][j] += a[i] * b[j];
        }
        if (t < 71) sts(cur ^ 1);
        __syncthreads();
    }

    float* C = &d_regpart[part * NROI * CI];
#pragma unroll
    for (int i = 0; i < 4; ++i)
#pragma unroll
        for (int j = 0; j < 4; ++j)
            C[(bm + tm + i) * CI + bn + tn + j] = acc[i][j];
}

// ============================================================
// K5: sum split-K parts + bias + relu + mean over T + selections
// grid 16 (b), 512 threads (j)
// ============================================================
__global__ void reduce_kernel(const float* __restrict__ re_b,
                              const int* __restrict__ cat,
                              float* __restrict__ out_labels) {
    int b = blockIdx.x, j = threadIdx.x;
    float bias = re_b[j];
    float pool = 0.0f;
#pragma unroll
    for (int nb = 0; nb < 4; ++nb) {
        float s = 0.0f;
#pragma unroll
        for (int t = 0; t < 8; ++t) {
            int r = (b * 8 + t) * 4 + nb;
            float v = bias;
#pragma unroll
            for (int p = 0; p < 4; ++p) v += d_regpart[p * NROI * CI + r * CI + j];
            s += fmaxf(v, 0.0f);
        }
        s *= 0.125f;
        if (nb >= 2) d_objf[(b * 2 + nb - 2) * CI + j] = s;   // argsort is identity (cats never 0)
        pool += s;
    }
    d_pooled[b * CI + j] = pool * 0.25f;
    if (j < 2) out_labels[b * 2 + j] = (float)cat[b * 4 + 2 + j];
}

// ============================================================
// K6: small dense head: C[m,:] = A[m,:512] @ B[512,N] + bias
// ============================================================
__global__ void small_mm(const float* __restrict__ A, const float* __restrict__ Bm,
                         const float* __restrict__ bias, float* __restrict__ C, int N) {
    __shared__ float As[512];
    int m = blockIdx.x, tid = threadIdx.x;
    for (int k = tid; k < 512; k += 256) As[k] = A[m * 512 + k];
    __syncthreads();
    for (int j = tid; j < N; j += 256) {
        float acc = bias[j];
#pragma unroll 4
        for (int k = 0; k < 512; ++k) acc += As[k] * Bm[k * N + j];
        C[m * N + j] = acc;
    }
}

// ============================================================
extern "C" void kernel_launch(void* const* d_in, const int* in_sizes, int n_in,
                              void* d_out, int out_size) {
    const float* x       = (const float*)d_in[0];
    const float* boxes   = (const float*)d_in[1];
    const int*   cat     = (const int*)d_in[2];
    const float* conv5_w = (const float*)d_in[3];
    const float* re_w    = (const float*)d_in[4];
    const float* re_b    = (const float*)d_in[5];
    const float* oc1_w   = (const float*)d_in[6];
    const float* oc1_b   = (const float*)d_in[7];
    const float* oc2_w   = (const float*)d_in[8];
    const float* oc2_b   = (const float*)d_in[9];
    const float* pr1_w   = (const float*)d_in[10];
    const float* pr1_b   = (const float*)d_in[11];
    const float* pr2_w   = (const float*)d_in[12];
    const float* pr2_b   = (const float*)d_in[13];

    float* out     = (float*)d_out;
    float* cls_out = out;                      // 16*174 = 2784
    float* obj_cls = out + 16 * 174;           // 32*301 = 9632
    float* labels  = out + 16 * 174 + 32 * 301; // 32

    float *p_objf, *p_pooled, *p_h1, *p_g1;
    cudaGetSymbolAddress((void**)&p_objf,   d_objf);
    cudaGetSymbolAddress((void**)&p_pooled, d_pooled);
    cudaGetSymbolAddress((void**)&p_h1,     d_h1);
    cudaGetSymbolAddress((void**)&p_g1,     d_g1);

    build_table<<<2, 256>>>(boxes);
    pool_kernel<<<dim3(CIN / 32, B_ * T_), 288>>>(x);
    gemm1<<<dim3(CI / 128, M1 / 128), 256>>>(conv5_w);
    gemm2<<<dim3(CI / 64, NROI / 64, 4), 256>>>(re_w);
    reduce_kernel<<<16, 512>>>(re_b, cat, labels);
    // object head: (32,512)@(512,512) then @(512,301)
    small_mm<<<32, 256>>>(p_objf, oc1_w, oc1_b, p_h1, 512);
    small_mm<<<32, 256>>>(p_h1, oc2_w, oc2_b, obj_cls, 301);
    // class head: (16,512)@(512,512) then @(512,174)
    small_mm<<<16, 256>>>(p_pooled, pr1_w, pr1_b, p_g1, 512);
    small_mm<<<16, 256>>>(p_g1, pr2_w, pr2_b, cls_out, 174);
}

// round 2
// speedup vs baseline: 2.4042x; 2.4042x over previous
#include <cuda_runtime.h>
#include <cuda_bf16.h>
#include <cstdint>

// ---------------- problem constants ----------------
#define B_    16
#define T_    8
#define CIN   2048
#define CI    512
#define HF    14
#define HW    196
#define NROI  512
#define M1    4608          // NROI*9
#define KFEAT 4608          // CI*9
#define NPART 8             // split-K parts for gemm2

// ---------------- scratch (static device memory) ----------------
__device__ __nv_bfloat16 d_roisH[(size_t)M1 * CIN];
__device__ __nv_bfloat16 d_roisL[(size_t)M1 * CIN];
__device__ __nv_bfloat16 d_wH[(size_t)CI * CIN];
__device__ __nv_bfloat16 d_wL[(size_t)CI * CIN];
__device__ __nv_bfloat16 d_rwH[(size_t)CI * KFEAT];   // re_w transposed+permuted [n][bin*512+o]
__device__ __nv_bfloat16 d_rwL[(size_t)CI * KFEAT];
__device__ __nv_bfloat16 d_featsH[(size_t)NROI * KFEAT]; // [roi][bin*512+o]
__device__ __nv_bfloat16 d_featsL[(size_t)NROI * KFEAT];
__device__ float d_regpart[(size_t)NPART * NROI * CI];
__device__ float d_objf[32 * CI];
__device__ float d_pooled[16 * CI];
__device__ float d_h1[32 * CI];
__device__ float d_g1[16 * CI];
__device__ int   d_tidx[NROI * 9 * 16];
__device__ float d_tw[NROI * 9 * 16];

// ---------------- PTX helpers ----------------
__device__ __forceinline__ uint32_t sm_u32(const void* p) {
    return (uint32_t)__cvta_generic_to_shared(p);
}
__device__ __forceinline__ void cpa16(uint32_t dst, const void* src) {
    asm volatile("cp.async.cg.shared.global [%0], [%1], 16;\n" :: "r"(dst), "l"(src));
}
__device__ __forceinline__ void cpa_commit() {
    asm volatile("cp.async.commit_group;\n" ::: "memory");
}
__device__ __forceinline__ void cpa_wait0() {
    asm volatile("cp.async.wait_group 0;\n" ::: "memory");
}
__device__ __forceinline__ void ldsm4(uint32_t* r, uint32_t addr) {
    asm volatile("ldmatrix.sync.aligned.m8n8.x4.shared.b16 {%0,%1,%2,%3}, [%4];"
                 : "=r"(r[0]), "=r"(r[1]), "=r"(r[2]), "=r"(r[3]) : "r"(addr));
}
__device__ __forceinline__ void mma16816(float* c, const uint32_t* a, uint32_t b0, uint32_t b1) {
    asm volatile("mma.sync.aligned.m16n8k16.row.col.f32.bf16.bf16.f32 "
                 "{%0,%1,%2,%3},{%4,%5,%6,%7},{%8,%9},{%0,%1,%2,%3};"
                 : "+f"(c[0]), "+f"(c[1]), "+f"(c[2]), "+f"(c[3])
                 : "r"(a[0]), "r"(a[1]), "r"(a[2]), "r"(a[3]), "r"(b0), "r"(b1));
}

// ============================================================
// K1: ROI-align tap table
// ============================================================
__global__ void build_table(const float* __restrict__ boxes) {
    int roi = blockIdx.x * blockDim.x + threadIdx.x;
    if (roi >= NROI) return;
    float cx = boxes[roi * 4 + 0], cy = boxes[roi * 4 + 1];
    float w  = boxes[roi * 4 + 2], h  = boxes[roi * 4 + 3];
    const float s = 14.0f / 224.0f;
    float x1 = (cx - 0.5f * w) * 224.0f * s;
    float y1 = (cy - 0.5f * h) * 224.0f * s;
    float x2 = (cx + 0.5f * w) * 224.0f * s;
    float y2 = (cy + 0.5f * h) * 224.0f * s;
    float rw = fmaxf(x2 - x1, 1.0f), rh = fmaxf(y2 - y1, 1.0f);
    float bw = rw / 3.0f, bh = rh / 3.0f;

    float ys[6], xs[6];
#pragma unroll
    for (int p = 0; p < 3; ++p)
#pragma unroll
        for (int i = 0; i < 2; ++i) {
            ys[p * 2 + i] = y1 + p * bh + (i + 0.5f) * bh * 0.5f;
            xs[p * 2 + i] = x1 + p * bw + (i + 0.5f) * bw * 0.5f;
        }

#pragma unroll
    for (int ph = 0; ph < 3; ++ph)
#pragma unroll
        for (int pw = 0; pw < 3; ++pw) {
            int bin = ph * 3 + pw;
#pragma unroll
            for (int iy = 0; iy < 2; ++iy)
#pragma unroll
                for (int ix = 0; ix < 2; ++ix) {
                    int smp = iy * 2 + ix;
                    float yy = ys[ph * 2 + iy];
                    float xx = xs[pw * 2 + ix];
                    bool valid = (yy > -1.0f) && (yy < 14.0f) && (xx > -1.0f) && (xx < 14.0f);
                    float y = fminf(fmaxf(yy, 0.0f), 13.0f);
                    float x = fminf(fmaxf(xx, 0.0f), 13.0f);
                    int y0 = (int)floorf(y), x0 = (int)floorf(x);
                    int y1i = min(y0 + 1, 13), x1i = min(x0 + 1, 13);
                    float ly = y - (float)y0, lx = x - (float)x0;
                    float hy = 1.0f - ly, hx = 1.0f - lx;
                    float q = valid ? 0.25f : 0.0f;
                    int base = ((roi * 9 + bin) * 4 + smp) * 4;
                    d_tidx[base + 0] = y0 * HF + x0;  d_tw[base + 0] = hy * hx * q;
                    d_tidx[base + 1] = y0 * HF + x1i; d_tw[base + 1] = hy * lx * q;
                    d_tidx[base + 2] = y1i * HF + x0; d_tw[base + 2] = ly * hx * q;
                    d_tidx[base + 3] = y1i * HF + x1i; d_tw[base + 3] = ly * lx * q;
                }
        }
}

// ============================================================
// K2: pooling in 2048-ch space -> bf16 hi/lo
// ============================================================
__global__ __launch_bounds__(288) void pool_kernel(const float* __restrict__ x) {
    __shared__ float pl[32][197];
    __shared__ int   tix[576];
    __shared__ float twt[576];
    int bt = blockIdx.y;
    int c0 = blockIdx.x * 32;
    int tid = threadIdx.x;

    size_t base = ((size_t)(bt >> 3) * CIN + c0) * (size_t)(T_ * HW) + (size_t)(bt & 7) * HW;
    for (int i = tid; i < 32 * HW; i += 288) {
        int ci = i / HW, p = i - ci * HW;
        pl[ci][p] = x[base + (size_t)ci * (T_ * HW) + p];
    }
    int tb = bt * 576;
    for (int i = tid; i < 576; i += 288) {
        tix[i] = d_tidx[tb + i];
        twt[i] = d_tw[tb + i];
    }
    __syncthreads();

    for (int oid = tid; oid < 1152; oid += 288) {
        int ci = oid & 31;
        int e  = oid >> 5;
        const int*   ip = &tix[e * 16];
        const float* wp = &twt[e * 16];
        float acc = 0.0f;
#pragma unroll
        for (int t = 0; t < 16; ++t) acc += wp[t] * pl[ci][ip[t]];
        __nv_bfloat16 hb = __float2bfloat16_rn(acc);
        __nv_bfloat16 lb = __float2bfloat16_rn(acc - __bfloat162float(hb));
        size_t off = (size_t)(bt * 36 + e) * CIN + c0 + ci;
        d_roisH[off] = hb;
        d_roisL[off] = lb;
    }
}

// ============================================================
// K3a: convert conv5_w -> bf16 hi/lo  [o][k], already K-major
// ============================================================
__global__ void convw_kernel(const float* __restrict__ w) {
    int i = blockIdx.x * 256 + threadIdx.x;   // 512*2048 / 256 blocks
    float v = w[i];
    __nv_bfloat16 hb = __float2bfloat16_rn(v);
    d_wH[i] = hb;
    d_wL[i] = __float2bfloat16_rn(v - __bfloat162float(hb));
}

// ============================================================
// K3b: convert re_w -> transposed+permuted bf16 hi/lo
//      d_rw[n][bin*512+o] = re_w[(o*9+bin)*512+n]
// ============================================================
__global__ __launch_bounds__(256) void convrw_kernel(const float* __restrict__ w) {
    __shared__ float t[32][33];
    int o0 = blockIdx.x * 32, n0 = blockIdx.y * 32, bin = blockIdx.z;
    int tx = threadIdx.x & 31, ty = threadIdx.x >> 5;
    for (int r = ty; r < 32; r += 8)
        t[r][tx] = w[((size_t)((o0 + r) * 9 + bin)) * 512 + n0 + tx];
    __syncthreads();
    for (int r = ty; r < 32; r += 8) {
        float v = t[tx][r];
        __nv_bfloat16 hb = __float2bfloat16_rn(v);
        __nv_bfloat16 lb = __float2bfloat16_rn(v - __bfloat162float(hb));
        size_t off = (size_t)(n0 + r) * KFEAT + bin * 512 + o0 + tx;
        d_rwH[off] = hb;
        d_rwL[off] = lb;
    }
}

// ============================================================
// GEMM core: C[128x128] tile via bf16 split mma.sync (3 passes)
// smem: per stage 4 arrays [128 rows][SROW bf16], 80B row stride
// ============================================================
#define KT    32
#define SROW  40
#define TILE_E (128 * SROW)
#define STAGE_E (4 * TILE_E)
#define GSMEM_BYTES (2 * STAGE_E * 2)

__device__ __forceinline__ void gemm_core(
    const __nv_bfloat16* __restrict__ gAh, const __nv_bfloat16* __restrict__ gAl, int lda,
    const __nv_bfloat16* __restrict__ gBh, const __nv_bfloat16* __restrict__ gBl, int ldb,
    int bm, int bn, int kbase, int niter,
    __nv_bfloat16* sm, float (&acc)[4][4][4])
{
    int tid = threadIdx.x, lane = tid & 31, wid = tid >> 5;
    int wm = wid >> 2, wn = wid & 3;     // warp tile: m0 = wm*64, n0 = wn*32

    auto ldg = [&](int t) {
        int s = t & 1;
        int k0 = kbase + t * KT;
        __nv_bfloat16* base = sm + s * STAGE_E;
#pragma unroll
        for (int j = 0; j < 2; ++j) {
            int id = (tid << 1) + j;
            int row = id >> 2, c = id & 3;
            __nv_bfloat16* pd = base + row * SROW + c * 8;
            const __nv_bfloat16* sa = gAh + (size_t)(bm + row) * lda + k0 + c * 8;
            const __nv_bfloat16* sal = gAl + (size_t)(bm + row) * lda + k0 + c * 8;
            const __nv_bfloat16* sb = gBh + (size_t)(bn + row) * ldb + k0 + c * 8;
            const __nv_bfloat16* sbl = gBl + (size_t)(bn + row) * ldb + k0 + c * 8;
            cpa16(sm_u32(pd), sa);
            cpa16(sm_u32(pd + TILE_E), sal);
            cpa16(sm_u32(pd + 2 * TILE_E), sb);
            cpa16(sm_u32(pd + 3 * TILE_E), sbl);
        }
    };

    int ar  = wm * 64 + (lane & 15);
    int ac8 = (lane >> 4) * 8;                       // bf16 units
    int br  = wn * 32 + (lane & 7) + ((lane >> 4) << 3);
    int bc8 = ((lane >> 3) & 1) * 8;

    ldg(0); cpa_commit();

#pragma unroll 1
    for (int t = 0; t < niter; ++t) {
        cpa_wait0();
        __syncthreads();
        if (t + 1 < niter) { ldg(t + 1); cpa_commit(); }

        __nv_bfloat16* base = sm + (t & 1) * STAGE_E;
        const __nv_bfloat16* pAh = base;
        const __nv_bfloat16* pAl = base + TILE_E;
        const __nv_bfloat16* pBh = base + 2 * TILE_E;
        const __nv_bfloat16* pBl = base + 3 * TILE_E;

#pragma unroll
        for (int ks = 0; ks < 2; ++ks) {
            uint32_t ah[4][4], al[4][4], bh[2][4], bl[2][4];
#pragma unroll
            for (int mt = 0; mt < 4; ++mt) {
                ldsm4(ah[mt], sm_u32(pAh + (ar + mt * 16) * SROW + ks * 16 + ac8));
                ldsm4(al[mt], sm_u32(pAl + (ar + mt * 16) * SROW + ks * 16 + ac8));
            }
#pragma unroll
            for (int bt2 = 0; bt2 < 2; ++bt2) {
                ldsm4(bh[bt2], sm_u32(pBh + (br + bt2 * 16) * SROW + ks * 16 + bc8));
                ldsm4(bl[bt2], sm_u32(pBl + (br + bt2 * 16) * SROW + ks * 16 + bc8));
            }
#pragma unroll
            for (int mt = 0; mt < 4; ++mt)
#pragma unroll
                for (int nt = 0; nt < 4; ++nt) {
                    uint32_t b0h = bh[nt >> 1][(nt & 1) * 2], b1h = bh[nt >> 1][(nt & 1) * 2 + 1];
                    uint32_t b0l = bl[nt >> 1][(nt & 1) * 2], b1l = bl[nt >> 1][(nt & 1) * 2 + 1];
                    mma16816(acc[mt][nt], ah[mt], b0h, b1h);
                    mma16816(acc[mt][nt], al[mt], b0h, b1h);
                    mma16816(acc[mt][nt], ah[mt], b0l, b1l);
                }
        }
    }
}

// ============================================================
// K4: GEMM1: feats = rois2048[4608,2048] x conv5_w[512,2048]^T
//     epilogue writes bf16 hi/lo feats[roi][bin*512+o] (contiguous)
// ============================================================
__global__ __launch_bounds__(256) void gemm1k() {
    extern __shared__ __nv_bfloat16 sm[];
    int bm = blockIdx.y * 128, bn = blockIdx.x * 128;
    float acc[4][4][4];
#pragma unroll
    for (int a = 0; a < 4; ++a)
#pragma unroll
        for (int b = 0; b < 4; ++b)
#pragma unroll
            for (int c = 0; c < 4; ++c) acc[a][b][c] = 0.0f;

    gemm_core(d_roisH, d_roisL, CIN, d_wH, d_wL, CIN, bm, bn, 0, CIN / KT, sm, acc);

    int lane = threadIdx.x & 31, wid = threadIdx.x >> 5;
    int wm = wid >> 2, wn = wid & 3;
    int mrow = wm * 64 + (lane >> 2);
    int ncol = wn * 32 + ((lane & 3) << 1);
#pragma unroll
    for (int mt = 0; mt < 4; ++mt)
#pragma unroll
        for (int nt = 0; nt < 4; ++nt) {
            float* c = acc[mt][nt];
            int n = bn + ncol + nt * 8;
#pragma unroll
            for (int half = 0; half < 2; ++half) {
                int m = bm + mrow + mt * 16 + half * 8;
                int roi = m / 9, bin = m - roi * 9;
                size_t off = (size_t)roi * KFEAT + bin * 512 + n;
                float v0 = c[half * 2 + 0], v1 = c[half * 2 + 1];
                __nv_bfloat16 h0 = __float2bfloat16_rn(v0);
                __nv_bfloat16 h1 = __float2bfloat16_rn(v1);
                __nv_bfloat162 hp; hp.x = h0; hp.y = h1;
                __nv_bfloat162 lp;
                lp.x = __float2bfloat16_rn(v0 - __bfloat162float(h0));
                lp.y = __float2bfloat16_rn(v1 - __bfloat162float(h1));
                *(__nv_bfloat162*)&d_featsH[off] = hp;
                *(__nv_bfloat162*)&d_featsL[off] = lp;
            }
        }
}

// ============================================================
// K5: GEMM2 (split-K=8): regpart = feats[512,4608] x rw[512,4608]^T
// ============================================================
__global__ __launch_bounds__(256) void gemm2k() {
    extern __shared__ __nv_bfloat16 sm[];
    int bm = blockIdx.y * 128, bn = blockIdx.x * 128;
    int part = blockIdx.z;
    float acc[4][4][4];
#pragma unroll
    for (int a = 0; a < 4; ++a)
#pragma unroll
        for (int b = 0; b < 4; ++b)
#pragma unroll
            for (int c = 0; c < 4; ++c) acc[a][b][c] = 0.0f;

    gemm_core(d_featsH, d_featsL, KFEAT, d_rwH, d_rwL, KFEAT,
              bm, bn, part * (KFEAT / NPART), (KFEAT / NPART) / KT, sm, acc);

    int lane = threadIdx.x & 31, wid = threadIdx.x >> 5;
    int wm = wid >> 2, wn = wid & 3;
    int mrow = wm * 64 + (lane >> 2);
    int ncol = wn * 32 + ((lane & 3) << 1);
    float* C = d_regpart + (size_t)part * NROI * CI;
#pragma unroll
    for (int mt = 0; mt < 4; ++mt)
#pragma unroll
        for (int nt = 0; nt < 4; ++nt) {
            float* c = acc[mt][nt];
            int n = bn + ncol + nt * 8;
#pragma unroll
            for (int half = 0; half < 2; ++half) {
                int m = bm + mrow + mt * 16 + half * 8;
                *(float2*)&C[(size_t)m * CI + n] = make_float2(c[half * 2], c[half * 2 + 1]);
            }
        }
}

// ============================================================
// K6: sum split-K parts + bias + relu + mean over T + selections
// ============================================================
__global__ void reduce_kernel(const float* __restrict__ re_b,
                              const int* __restrict__ cat,
                              float* __restrict__ out_labels) {
    int b = blockIdx.x, j = threadIdx.x;
    float bias = re_b[j];
    float pool = 0.0f;
#pragma unroll
    for (int nb = 0; nb < 4; ++nb) {
        float s = 0.0f;
#pragma unroll
        for (int t = 0; t < 8; ++t) {
            int r = (b * 8 + t) * 4 + nb;
            float v = bias;
#pragma unroll
            for (int p = 0; p < NPART; ++p) v += d_regpart[(size_t)p * NROI * CI + (size_t)r * CI + j];
            s += fmaxf(v, 0.0f);
        }
        s *= 0.125f;
        if (nb >= 2) d_objf[(b * 2 + nb - 2) * CI + j] = s;   // argsort identity: cats never 0
        pool += s;
    }
    d_pooled[b * CI + j] = pool * 0.25f;
    if (j < 2) out_labels[b * 2 + j] = (float)cat[b * 4 + 2 + j];
}

// ============================================================
// K7: small dense head: C[m, j0:j0+64] = A[m,:512] @ B[:,j] + bias
// grid (m, nchunk), 256 threads, 4-way k-split + smem reduce
// ============================================================
__global__ __launch_bounds__(256) void small_mm(const float* __restrict__ A,
                                                const float* __restrict__ Bm,
                                                const float* __restrict__ bias,
                                                float* __restrict__ C, int N) {
    __shared__ float As[512];
    __shared__ float red[256];
    int m = blockIdx.x, j0 = blockIdx.y * 64;
    int tid = threadIdx.x, jl = tid & 63, ks = tid >> 6;
    for (int k = tid; k < 512; k += 256) As[k] = A[m * 512 + k];
    __syncthreads();
    int j = j0 + jl;
    float acc = 0.0f;
    if (j < N) {
        int k0 = ks * 128;
#pragma unroll 8
        for (int k = k0; k < k0 + 128; ++k) acc += As[k] * Bm[k * N + j];
    }
    red[tid] = acc;
    __syncthreads();
    if (tid < 64 && j < N)
        C[m * N + j] = red[tid] + red[tid + 64] + red[tid + 128] + red[tid + 192] + bias[j];
}

// ============================================================
extern "C" void kernel_launch(void* const* d_in, const int* in_sizes, int n_in,
                              void* d_out, int out_size) {
    const float* x       = (const float*)d_in[0];
    const float* boxes   = (const float*)d_in[1];
    const int*   cat     = (const int*)d_in[2];
    const float* conv5_w = (const float*)d_in[3];
    const float* re_w    = (const float*)d_in[4];
    const float* re_b    = (const float*)d_in[5];
    const float* oc1_w   = (const float*)d_in[6];
    const float* oc1_b   = (const float*)d_in[7];
    const float* oc2_w   = (const float*)d_in[8];
    const float* oc2_b   = (const float*)d_in[9];
    const float* pr1_w   = (const float*)d_in[10];
    const float* pr1_b   = (const float*)d_in[11];
    const float* pr2_w   = (const float*)d_in[12];
    const float* pr2_b   = (const float*)d_in[13];

    float* out     = (float*)d_out;
    float* cls_out = out;                       // 16*174
    float* obj_cls = out + 16 * 174;            // 32*301
    float* labels  = out + 16 * 174 + 32 * 301; // 32

    float *p_objf, *p_pooled, *p_h1, *p_g1;
    cudaGetSymbolAddress((void**)&p_objf,   d_objf);
    cudaGetSymbolAddress((void**)&p_pooled, d_pooled);
    cudaGetSymbolAddress((void**)&p_h1,     d_h1);
    cudaGetSymbolAddress((void**)&p_g1,     d_g1);

    cudaFuncSetAttribute(gemm1k, cudaFuncAttributeMaxDynamicSharedMemorySize, GSMEM_BYTES);
    cudaFuncSetAttribute(gemm2k, cudaFuncAttributeMaxDynamicSharedMemorySize, GSMEM_BYTES);

    build_table<<<2, 256>>>(boxes);
    convw_kernel<<<(CI * CIN) / 256, 256>>>(conv5_w);
    convrw_kernel<<<dim3(16, 16, 9), 256>>>(re_w);
    pool_kernel<<<dim3(CIN / 32, B_ * T_), 288>>>(x);
    gemm1k<<<dim3(CI / 128, M1 / 128), 256, GSMEM_BYTES>>>();
    gemm2k<<<dim3(CI / 128, NROI / 128, NPART), 256, GSMEM_BYTES>>>();
    reduce_kernel<<<16, 512>>>(re_b, cat, labels);
    small_mm<<<dim3(32, 8), 256>>>(p_objf, oc1_w, oc1_b, p_h1, 512);
    small_mm<<<dim3(32, 5), 256>>>(p_h1, oc2_w, oc2_b, obj_cls, 301);
    small_mm<<<dim3(16, 8), 256>>>(p_pooled, pr1_w, pr1_b, p_g1, 512);
    small_mm<<<dim3(16, 3), 256>>>(p_g1, pr2_w, pr2_b, cls_out, 174);
}